// round 6
// baseline (speedup 1.0000x reference)
#include <cuda_runtime.h>
#include <math.h>

#define NNODES 100000
#define NEDGES 1600000
#define NEG_SLOPE 0.2f
#define BN_EPS_C 1e-5f
#define EB 6250        // NEDGES / 256
#define NB98 98        // ceil(NNODES / 1024)
#define GB64 1563      // ceil(NNODES / 64)
#define GB256 391      // ceil(NNODES / 256)
#define WARPB 12500    // NNODES / 8 warp-per-node blocks

#define FLAG_A 0x10000000
#define FLAG_P 0x20000000
#define VAL_MASK 0x0FFFFFFF

// ----------------------------- scratch (device globals; allocation-free) ----
__device__ float g_tmpH[NNODES * 64];
__device__ float g_tmpX[NNODES * 64];   // x2 @ W1b (precomputed)
__device__ float g_h0[NNODES * 64];
__device__ float g_h1[NNODES * 64];
__device__ float g_tmpS[NNODES * 16];
__device__ float g_as[NNODES], g_ad[NNODES];
__device__ float g_as2[NNODES], g_ad2[NNODES];
__device__ int   g_deg1[NNODES], g_off1[NNODES];
__device__ int   g_deg2[NNODES], g_off2[NNODES];
__device__ int   g_cursor1[NNODES], g_cursor2[NNODES];
__device__ int   g_srcs1[NEDGES], g_srcs2[NEDGES];
__device__ int   g_state1[NB98], g_state2[NB98];
__device__ float g_bnsum[16], g_bnsumsq[16];

__device__ __forceinline__ float lrelu(float x) { return x > 0.f ? x : NEG_SLOPE * x; }
__device__ __forceinline__ float elu1(float x)  { return x > 0.f ? x : expm1f(x); }

// ============================ device building blocks ========================

__device__ __forceinline__ void dev_count(const int* __restrict__ ei,
                                          int* __restrict__ deg, int bid) {
    int e = bid * 256 + threadIdx.x;
    if (e < NEDGES) atomicAdd(&deg[__ldg(&ei[NEDGES + e])], 1);
}

__device__ __forceinline__ void dev_scatter(const int* __restrict__ ei,
                                            int* __restrict__ cursor,
                                            int* __restrict__ srcs, int bid) {
    int e = bid * 256 + threadIdx.x;
    if (e < NEDGES) {
        int src = __ldg(&ei[e]);
        int dst = __ldg(&ei[NEDGES + e]);
        srcs[atomicAdd(&cursor[dst], 1)] = src;
    }
}

// single-pass scan with decoupled lookback. 256 thr, 1024 elems/block, 98 blocks.
__device__ void dev_scan_lookback(const int* __restrict__ deg, int* __restrict__ off,
                                  int* __restrict__ cur, int* __restrict__ state, int lb) {
    __shared__ int sh[256];
    __shared__ int s_prefix;
    int tid = threadIdx.x;
    int base = lb * 1024 + tid * 4;
    int4 v = make_int4(0, 0, 0, 0);
    if (base + 3 < NNODES) {
        v = *reinterpret_cast<const int4*>(&deg[base]);
    } else {
        if (base + 0 < NNODES) v.x = deg[base + 0];
        if (base + 1 < NNODES) v.y = deg[base + 1];
        if (base + 2 < NNODES) v.z = deg[base + 2];
    }
    int lsum = v.x + v.y + v.z + v.w;
    sh[tid] = lsum;
    __syncthreads();
    for (int d = 1; d < 256; d <<= 1) {
        int t = (tid >= d) ? sh[tid - d] : 0;
        __syncthreads();
        if (tid >= d) sh[tid] += t;
        __syncthreads();
    }
    int total = sh[255];
    int ex_in = sh[tid] - lsum;

    if (tid < 32) {
        if (tid == 0) {
            __threadfence();
            if (lb == 0) atomicExch(&state[0], FLAG_P | total);
            else         atomicExch(&state[lb], FLAG_A | total);
        }
        __syncwarp();
        int ex = 0;
        int end = lb;
        while (end > 0) {
            int start = end - 32; if (start < 0) start = 0;
            int idx = start + tid;
            int s = 0;
            if (idx < end) { do { s = atomicAdd(&state[idx], 0); } while (s == 0); }
            unsigned pmask = __ballot_sync(0xffffffffu, (idx < end) && (s >= FLAG_P));
            int lead = pmask ? (31 - __clz(pmask)) : 0;
            int contrib = ((idx < end) && (tid >= lead)) ? (s & VAL_MASK) : 0;
            #pragma unroll
            for (int o = 16; o > 0; o >>= 1) contrib += __shfl_xor_sync(0xffffffffu, contrib, o);
            ex += contrib;
            end = pmask ? 0 : start;
        }
        if (tid == 0) {
            if (lb > 0) { __threadfence(); atomicExch(&state[lb], FLAG_P | (ex + total)); }
            s_prefix = ex;
        }
    }
    __syncthreads();
    int p = s_prefix + ex_in;
    int e0 = p, e1 = e0 + v.x, e2 = e1 + v.y, e3 = e2 + v.z;
    if (base + 3 < NNODES) {
        *reinterpret_cast<int4*>(&off[base]) = make_int4(e0, e1, e2, e3);
        *reinterpret_cast<int4*>(&cur[base]) = make_int4(e0, e1, e2, e3);
    } else {
        if (base + 0 < NNODES) { off[base + 0] = e0; cur[base + 0] = e0; }
        if (base + 1 < NNODES) { off[base + 1] = e1; cur[base + 1] = e1; }
        if (base + 2 < NNODES) { off[base + 2] = e2; cur[base + 2] = e2; }
    }
}

// GEMM (+ optional P add, + optional attention dots). 256 thr, K=64 (or 128).
template <int BN, bool TWO, bool ADDP, bool DOTS>
__device__ void dev_gemm(const float* __restrict__ A1, const float* __restrict__ A2,
                         const float* __restrict__ P, const float* __restrict__ W,
                         const float* __restrict__ a_src, const float* __restrict__ a_dst,
                         float* __restrict__ C, float* __restrict__ asv,
                         float* __restrict__ adv, int bid) {
    constexpr int K = TWO ? 128 : 64;
    constexpr int NCOLT = BN / 4;
    constexpr int NROWT = 256 / NCOLT;
    constexpr int BM = NROWT * 4;
    __shared__ float Ws[K * BN];

    int tid = threadIdx.x;
    for (int idx = tid; idx < K * BN; idx += 256) Ws[idx] = W[idx];
    __syncthreads();

    int tcol = tid % NCOLT;
    int trow = tid / NCOLT;
    int n0 = tcol * 4;
    int r0 = bid * BM + trow * 4;

    float acc[4][4] = {};
    bool val[4];
    #pragma unroll
    for (int i = 0; i < 4; i++) val[i] = (r0 + i) < NNODES;

    #pragma unroll
    for (int seg = 0; seg < (TWO ? 2 : 1); seg++) {
        const float* A = (seg == 0) ? A1 : A2;
        #pragma unroll 4
        for (int k4 = 0; k4 < 16; k4++) {
            float a[4][4];
            #pragma unroll
            for (int i = 0; i < 4; i++) {
                float4 t = val[i]
                    ? *reinterpret_cast<const float4*>(&A[(size_t)(r0 + i) * 64 + k4 * 4])
                    : make_float4(0.f, 0.f, 0.f, 0.f);
                a[i][0] = t.x; a[i][1] = t.y; a[i][2] = t.z; a[i][3] = t.w;
            }
            #pragma unroll
            for (int s = 0; s < 4; s++) {
                float4 wv = *reinterpret_cast<const float4*>(
                    &Ws[(seg * 64 + k4 * 4 + s) * BN + n0]);
                #pragma unroll
                for (int i = 0; i < 4; i++) {
                    acc[i][0] += a[i][s] * wv.x;
                    acc[i][1] += a[i][s] * wv.y;
                    acc[i][2] += a[i][s] * wv.z;
                    acc[i][3] += a[i][s] * wv.w;
                }
            }
        }
    }
    if (ADDP) {
        #pragma unroll
        for (int i = 0; i < 4; i++) {
            if (val[i]) {
                float4 pv = *reinterpret_cast<const float4*>(&P[(size_t)(r0 + i) * BN + n0]);
                acc[i][0] += pv.x; acc[i][1] += pv.y; acc[i][2] += pv.z; acc[i][3] += pv.w;
            }
        }
    }
    #pragma unroll
    for (int i = 0; i < 4; i++) {
        if (val[i]) {
            *reinterpret_cast<float4*>(&C[(size_t)(r0 + i) * BN + n0]) =
                make_float4(acc[i][0], acc[i][1], acc[i][2], acc[i][3]);
        }
    }
    if (DOTS) {
        float4 as4 = *reinterpret_cast<const float4*>(&a_src[n0]);
        float4 ad4 = *reinterpret_cast<const float4*>(&a_dst[n0]);
        float s_par[4], d_par[4];
        #pragma unroll
        for (int i = 0; i < 4; i++) {
            s_par[i] = acc[i][0] * as4.x + acc[i][1] * as4.y + acc[i][2] * as4.z + acc[i][3] * as4.w;
            d_par[i] = acc[i][0] * ad4.x + acc[i][1] * ad4.y + acc[i][2] * ad4.z + acc[i][3] * ad4.w;
        }
        #pragma unroll
        for (int o = NCOLT / 2; o > 0; o >>= 1) {
            #pragma unroll
            for (int i = 0; i < 4; i++) {
                s_par[i] += __shfl_xor_sync(0xffffffffu, s_par[i], o);
                d_par[i] += __shfl_xor_sync(0xffffffffu, d_par[i], o);
            }
        }
        if (tcol == 0) {
            #pragma unroll
            for (int i = 0; i < 4; i++) {
                if (val[i]) { asv[r0 + i] = s_par[i]; adv[r0 + i] = d_par[i]; }
            }
        }
    }
}

// GAT aggregation F=64, warp per node, float2 feature layout.
// EPI: 1 = write tmpS partial (h_out @ W2p), 2 = accumulate + layer-2 dots.
template <int EPI>
__device__ void dev_agg64(const float* __restrict__ h, const float* __restrict__ asv,
                          const float* __restrict__ adv, const int* __restrict__ off,
                          const int* __restrict__ deg, const int* __restrict__ srcs,
                          const float* __restrict__ bias, float* __restrict__ out,
                          const float* __restrict__ W2p, float* __restrict__ tmpS,
                          const float* __restrict__ as2v, const float* __restrict__ ad2v,
                          float* __restrict__ asv2, float* __restrict__ adv2, int bid) {
    __shared__ float2 w2s[16][32];
    for (int t = threadIdx.x; t < 512; t += 256) {
        int c = t >> 5, l = t & 31;
        w2s[c][l] = make_float2(__ldg(&W2p[(2 * l) * 16 + c]), __ldg(&W2p[(2 * l + 1) * 16 + c]));
    }
    __syncthreads();

    const int i = bid * 8 + (threadIdx.x >> 5);
    const int lane = threadIdx.x & 31;
    const float ad_i = __ldg(&adv[i]);
    const int base = __ldg(&off[i]);
    const int d = __ldg(&deg[i]);

    float wself = __expf(lrelu(__ldg(&asv[i]) + ad_i));
    float denom = wself;
    float2 hs = *reinterpret_cast<const float2*>(&h[(size_t)i * 64 + 2 * lane]);
    float acc0 = wself * hs.x;
    float acc1 = wself * hs.y;

    for (int k0 = 0; k0 < d; k0 += 32) {
        int kk = k0 + lane;
        int j = 0; float wv = 0.f;
        if (kk < d) {
            j = __ldg(&srcs[base + kk]);
            wv = __expf(lrelu(__ldg(&asv[j]) + ad_i));
        }
        float ws = wv;
        #pragma unroll
        for (int o = 16; o > 0; o >>= 1) ws += __shfl_xor_sync(0xffffffffu, ws, o);
        denom += ws;

        int cnt = min(32, d - k0);
        int k = 0;
        for (; k + 4 <= cnt; k += 4) {
            int j0 = __shfl_sync(0xffffffffu, j, k);
            int j1 = __shfl_sync(0xffffffffu, j, k + 1);
            int j2 = __shfl_sync(0xffffffffu, j, k + 2);
            int j3 = __shfl_sync(0xffffffffu, j, k + 3);
            float w0 = __shfl_sync(0xffffffffu, wv, k);
            float w1 = __shfl_sync(0xffffffffu, wv, k + 1);
            float w2 = __shfl_sync(0xffffffffu, wv, k + 2);
            float w3 = __shfl_sync(0xffffffffu, wv, k + 3);
            float2 H0 = *reinterpret_cast<const float2*>(&h[(size_t)j0 * 64 + 2 * lane]);
            float2 H1 = *reinterpret_cast<const float2*>(&h[(size_t)j1 * 64 + 2 * lane]);
            float2 H2 = *reinterpret_cast<const float2*>(&h[(size_t)j2 * 64 + 2 * lane]);
            float2 H3 = *reinterpret_cast<const float2*>(&h[(size_t)j3 * 64 + 2 * lane]);
            acc0 += w0 * H0.x; acc1 += w0 * H0.y;
            acc0 += w1 * H1.x; acc1 += w1 * H1.y;
            acc0 += w2 * H2.x; acc1 += w2 * H2.y;
            acc0 += w3 * H3.x; acc1 += w3 * H3.y;
        }
        for (; k < cnt; k++) {
            int jj = __shfl_sync(0xffffffffu, j, k);
            float wk = __shfl_sync(0xffffffffu, wv, k);
            float2 H = *reinterpret_cast<const float2*>(&h[(size_t)jj * 64 + 2 * lane]);
            acc0 += wk * H.x; acc1 += wk * H.y;
        }
    }
    float inv = 1.0f / (denom + 1e-16f);
    float2 bv = *reinterpret_cast<const float2*>(&bias[2 * lane]);
    float v0 = elu1(acc0 * inv + bv.x);
    float v1 = elu1(acc1 * inv + bv.y);
    *reinterpret_cast<float2*>(&out[(size_t)i * 64 + 2 * lane]) = make_float2(v0, v1);

    // ---- fused layer-2 GEMM contribution: tmpS[i,:] (+)= h_out[i,:] @ W2p ----
    float outc = 0.f;
    #pragma unroll
    for (int c = 0; c < 16; c++) {
        float2 w = w2s[c][lane];
        float p = v0 * w.x + v1 * w.y;
        #pragma unroll
        for (int o = 16; o > 0; o >>= 1) p += __shfl_xor_sync(0xffffffffu, p, o);
        if (lane == c) outc = p;
    }
    if (EPI == 1) {
        if (lane < 16) tmpS[(size_t)i * 16 + lane] = outc;
    } else {
        if (lane < 16) {
            float t = tmpS[(size_t)i * 16 + lane] + outc;
            tmpS[(size_t)i * 16 + lane] = t;
            float sv = t * __ldg(&as2v[lane]);
            float dv = t * __ldg(&ad2v[lane]);
            #pragma unroll
            for (int o = 8; o > 0; o >>= 1) {
                sv += __shfl_xor_sync(0x0000ffffu, sv, o);
                dv += __shfl_xor_sync(0x0000ffffu, dv, o);
            }
            if (lane == 0) { asv2[i] = sv; adv2[i] = dv; }
        }
    }
}

// ============================ fused kernels =================================

__global__ void k_zero() {
    int i = blockIdx.x * blockDim.x + threadIdx.x;
    if (i < NNODES) { g_deg1[i] = 0; g_deg2[i] = 0; }
    if (i < NB98) { g_state1[i] = 0; g_state2[i] = 0; }
    if (i < 16) { g_bnsum[i] = 0.f; g_bnsumsq[i] = 0.f; }
}

// L2: count1 || gemm0(+dots)
__global__ void __launch_bounds__(256) k_count1_gemm0(
    const int* __restrict__ ei1, const float* __restrict__ x1,
    const float* __restrict__ W0, const float* __restrict__ as0,
    const float* __restrict__ ad0) {
    if (blockIdx.x < EB) dev_count(ei1, g_deg1, blockIdx.x);
    else dev_gemm<64, false, false, true>(x1, nullptr, nullptr, W0, as0, ad0,
                                          g_tmpH, g_as, g_ad, blockIdx.x - EB);
}

// L3: scan1(lookback) || count2 || gemmX = x2 @ W1b
__global__ void __launch_bounds__(256) k_scan1_count2_gemmX(
    const int* __restrict__ ei2, const float* __restrict__ x2,
    const float* __restrict__ W1) {
    if (blockIdx.x < NB98)
        dev_scan_lookback(g_deg1, g_off1, g_cursor1, g_state1, blockIdx.x);
    else if (blockIdx.x < NB98 + EB)
        dev_count(ei2, g_deg2, blockIdx.x - NB98);
    else
        dev_gemm<64, false, false, false>(x2, nullptr, nullptr, W1 + 64 * 64,
                                          nullptr, nullptr, g_tmpX, nullptr, nullptr,
                                          blockIdx.x - NB98 - EB);
}

// L4: scan2(lookback) || scatter1
__global__ void __launch_bounds__(256) k_scan2_scatter1(const int* __restrict__ ei1) {
    if (blockIdx.x < NB98)
        dev_scan_lookback(g_deg2, g_off2, g_cursor2, g_state2, blockIdx.x);
    else
        dev_scatter(ei1, g_cursor1, g_srcs1, blockIdx.x - NB98);
}

// L5: agg0 (+tmpS partial = h0@W2a) || scatter2
__global__ void __launch_bounds__(256) k_agg0_scatter2(
    const int* __restrict__ ei2, const float* __restrict__ b0,
    const float* __restrict__ W2) {
    if (blockIdx.x < WARPB)
        dev_agg64<1>(g_tmpH, g_as, g_ad, g_off1, g_deg1, g_srcs1, b0, g_h0,
                     W2, g_tmpS, nullptr, nullptr, nullptr, nullptr, blockIdx.x);
    else
        dev_scatter(ei2, g_cursor2, g_srcs2, blockIdx.x - WARPB);
}

// L6: gemm1' = h0 @ W1a + tmpX (+dots)
__global__ void __launch_bounds__(256) k_gemm1(
    const float* __restrict__ W1, const float* __restrict__ as1,
    const float* __restrict__ ad1) {
    dev_gemm<64, false, true, true>(g_h0, nullptr, g_tmpX, W1, as1, ad1,
                                    g_tmpH, g_as, g_ad, blockIdx.x);
}

// L7: agg1 (+tmpS += h1@W2b, + layer-2 dots)
__global__ void __launch_bounds__(256) k_agg1(
    const float* __restrict__ b1, const float* __restrict__ W2,
    const float* __restrict__ as2, const float* __restrict__ ad2) {
    dev_agg64<2>(g_tmpH, g_as, g_ad, g_off2, g_deg2, g_srcs2, b1, g_h1,
                 W2 + 64 * 16, g_tmpS, as2, ad2, g_as2, g_ad2, blockIdx.x);
}

// L8: agg layer2 (F=16) with fused BN statistics
__global__ void __launch_bounds__(256) k_agg2_bn(
    const float* __restrict__ b2, float* __restrict__ out) {
    __shared__ float shs[16], shs2[16];
    if (threadIdx.x < 16) { shs[threadIdx.x] = 0.f; shs2[threadIdx.x] = 0.f; }
    __syncthreads();

    const float* __restrict__ h = g_tmpS;
    const int i = blockIdx.x * 8 + (threadIdx.x >> 5);
    const int lane = threadIdx.x & 31;
    const int e = lane >> 4;
    const int f = lane & 15;
    const float ad_i = __ldg(&g_ad2[i]);
    const int base = __ldg(&g_off2[i]);
    const int d = __ldg(&g_deg2[i]);

    float wself = __expf(lrelu(__ldg(&g_as2[i]) + ad_i));
    float denom = wself;
    float acc = (e == 0) ? wself * h[(size_t)i * 16 + f] : 0.f;

    for (int k0 = 0; k0 < d; k0 += 32) {
        int kk = k0 + lane;
        int j = 0; float wv = 0.f;
        if (kk < d) {
            j = __ldg(&g_srcs2[base + kk]);
            wv = __expf(lrelu(__ldg(&g_as2[j]) + ad_i));
        }
        float ws = wv;
        #pragma unroll
        for (int o = 16; o > 0; o >>= 1) ws += __shfl_xor_sync(0xffffffffu, ws, o);
        denom += ws;

        int cnt = min(32, d - k0);
        int k = 0;
        for (; k + 4 <= cnt; k += 4) {
            int ja = __shfl_sync(0xffffffffu, j, k + e);
            int jb = __shfl_sync(0xffffffffu, j, k + 2 + e);
            float wa = __shfl_sync(0xffffffffu, wv, k + e);
            float wb = __shfl_sync(0xffffffffu, wv, k + 2 + e);
            acc += wa * h[(size_t)ja * 16 + f] + wb * h[(size_t)jb * 16 + f];
        }
        for (; k < cnt; k += 2) {
            int km = min(k + e, 31);
            int ja = __shfl_sync(0xffffffffu, j, km);
            float wa = __shfl_sync(0xffffffffu, wv, km);
            if (k + e < cnt) acc += wa * h[(size_t)ja * 16 + f];
        }
    }
    acc += __shfl_xor_sync(0xffffffffu, acc, 16);
    float inv = 1.0f / (denom + 1e-16f);
    if (e == 0) {
        float v = acc * inv + __ldg(&b2[f]);
        out[(size_t)i * 16 + f] = v;
        atomicAdd(&shs[f], v);
        atomicAdd(&shs2[f], v * v);
    }
    __syncthreads();
    if (threadIdx.x < 16) {
        atomicAdd(&g_bnsum[threadIdx.x], shs[threadIdx.x]);
        atomicAdd(&g_bnsumsq[threadIdx.x], shs2[threadIdx.x]);
    }
}

// L9: BN + log_softmax in place
__global__ void __launch_bounds__(256) k_bn_lsm(
    float* __restrict__ out, const float* __restrict__ gamma,
    const float* __restrict__ beta) {
    int i = blockIdx.x * blockDim.x + threadIdx.x;
    if (i >= NNODES) return;
    float y[16];
    float maxv = -1e30f;
    const float invN = 1.0f / (float)NNODES;
    #pragma unroll
    for (int c = 0; c < 16; c++) {
        float mu = g_bnsum[c] * invN;
        float var = g_bnsumsq[c] * invN - mu * mu;
        float v = out[(size_t)i * 16 + c];
        float yy = (v - mu) * rsqrtf(var + BN_EPS_C) * gamma[c] + beta[c];
        y[c] = yy;
        maxv = fmaxf(maxv, yy);
    }
    float s = 0.f;
    #pragma unroll
    for (int c = 0; c < 16; c++) s += expf(y[c] - maxv);
    float lse = maxv + logf(s);
    #pragma unroll
    for (int c = 0; c < 16; c++) out[(size_t)i * 16 + c] = y[c] - lse;
}

// ----------------------------- driver ---------------------------------------
extern "C" void kernel_launch(void* const* d_in, const int* in_sizes, int n_in,
                              void* d_out, int out_size) {
    const float* x1    = (const float*)d_in[0];
    const float* x2    = (const float*)d_in[1];
    const int*   ei1   = (const int*)d_in[2];
    const int*   ei2   = (const int*)d_in[3];
    const float* W0    = (const float*)d_in[4];
    const float* asrc0 = (const float*)d_in[5];
    const float* adst0 = (const float*)d_in[6];
    const float* b0    = (const float*)d_in[7];
    const float* W1    = (const float*)d_in[8];
    const float* asrc1 = (const float*)d_in[9];
    const float* adst1 = (const float*)d_in[10];
    const float* b1    = (const float*)d_in[11];
    const float* W2    = (const float*)d_in[12];
    const float* asrc2 = (const float*)d_in[13];
    const float* adst2 = (const float*)d_in[14];
    const float* b2    = (const float*)d_in[15];
    const float* gamma = (const float*)d_in[16];
    const float* beta  = (const float*)d_in[17];
    float* out = (float*)d_out;

    k_zero<<<GB256, 256>>>();                                            // L1
    k_count1_gemm0<<<EB + GB64, 256>>>(ei1, x1, W0, asrc0, adst0);       // L2
    k_scan1_count2_gemmX<<<NB98 + EB + GB64, 256>>>(ei2, x2, W1);        // L3
    k_scan2_scatter1<<<NB98 + EB, 256>>>(ei1);                           // L4
    k_agg0_scatter2<<<WARPB + EB, 256>>>(ei2, b0, W2);                   // L5
    k_gemm1<<<GB64, 256>>>(W1, asrc1, adst1);                            // L6
    k_agg1<<<WARPB, 256>>>(b1, W2, asrc2, adst2);                        // L7
    k_agg2_bn<<<WARPB, 256>>>(b2, out);                                  // L8
    k_bn_lsm<<<GB256, 256>>>(out, gamma, beta);                          // L9
}

// round 10
// speedup vs baseline: 1.3632x; 1.3632x over previous
#include <cuda_runtime.h>
#include <math.h>

#define NNODES 100000
#define NEDGES 1600000
#define NEG_SLOPE 0.2f
#define BN_EPS_C 1e-5f
#define EB 6250        // NEDGES / 256
#define NB98 98        // ceil(NNODES / 1024)
#define GB64 1563      // ceil(NNODES / 64)
#define GB256 391      // ceil(NNODES / 256)
#define WARPB 12500    // NNODES / 8 warp-per-node blocks

#define FLAG_A 0x10000000
#define FLAG_P 0x20000000
#define VAL_MASK 0x0FFFFFFF

// ----------------------------- scratch (device globals; allocation-free) ----
__device__ float g_tmpH[NNODES * 64];
__device__ float g_h0[NNODES * 64];
__device__ float g_h1[NNODES * 64];
__device__ float g_tmpS[NNODES * 16];
__device__ float g_as[NNODES], g_ad[NNODES];
__device__ int   g_deg1[NNODES], g_off1[NNODES];
__device__ int   g_deg2[NNODES], g_off2[NNODES];
__device__ int   g_cursor1[NNODES], g_cursor2[NNODES];
__device__ int   g_srcs1[NEDGES], g_srcs2[NEDGES];
__device__ int   g_state1[NB98], g_state2[NB98];
__device__ float g_bnsum[16], g_bnsumsq[16];

__device__ __forceinline__ float lrelu(float x) { return x > 0.f ? x : NEG_SLOPE * x; }
__device__ __forceinline__ float elu1(float x)  { return x > 0.f ? x : expm1f(x); }

// ============================ device building blocks ========================

__device__ __forceinline__ void dev_count(const int* __restrict__ ei,
                                          int* __restrict__ deg, int bid) {
    int e = bid * 256 + threadIdx.x;
    if (e < NEDGES) atomicAdd(&deg[__ldg(&ei[NEDGES + e])], 1);
}

__device__ __forceinline__ void dev_scatter(const int* __restrict__ ei,
                                            int* __restrict__ cursor,
                                            int* __restrict__ srcs, int bid) {
    int e = bid * 256 + threadIdx.x;
    if (e < NEDGES) {
        int src = __ldg(&ei[e]);
        int dst = __ldg(&ei[NEDGES + e]);
        srcs[atomicAdd(&cursor[dst], 1)] = src;
    }
}

// single-pass scan with decoupled lookback. 256 thr, 1024 elems/block, 98 blocks.
__device__ void dev_scan_lookback(const int* __restrict__ deg, int* __restrict__ off,
                                  int* __restrict__ cur, int* __restrict__ state, int lb) {
    __shared__ int sh[256];
    __shared__ int s_prefix;
    int tid = threadIdx.x;
    int base = lb * 1024 + tid * 4;
    int4 v = make_int4(0, 0, 0, 0);
    if (base + 3 < NNODES) {
        v = *reinterpret_cast<const int4*>(&deg[base]);
    } else {
        if (base + 0 < NNODES) v.x = deg[base + 0];
        if (base + 1 < NNODES) v.y = deg[base + 1];
        if (base + 2 < NNODES) v.z = deg[base + 2];
    }
    int lsum = v.x + v.y + v.z + v.w;
    sh[tid] = lsum;
    __syncthreads();
    for (int d = 1; d < 256; d <<= 1) {
        int t = (tid >= d) ? sh[tid - d] : 0;
        __syncthreads();
        if (tid >= d) sh[tid] += t;
        __syncthreads();
    }
    int total = sh[255];
    int ex_in = sh[tid] - lsum;

    if (tid < 32) {
        if (tid == 0) {
            __threadfence();
            if (lb == 0) atomicExch(&state[0], FLAG_P | total);
            else         atomicExch(&state[lb], FLAG_A | total);
        }
        __syncwarp();
        int ex = 0;
        int end = lb;
        while (end > 0) {
            int start = end - 32; if (start < 0) start = 0;
            int idx = start + tid;
            int s = 0;
            if (idx < end) { do { s = atomicAdd(&state[idx], 0); } while (s == 0); }
            unsigned pmask = __ballot_sync(0xffffffffu, (idx < end) && (s >= FLAG_P));
            int lead = pmask ? (31 - __clz(pmask)) : 0;
            int contrib = ((idx < end) && (tid >= lead)) ? (s & VAL_MASK) : 0;
            #pragma unroll
            for (int o = 16; o > 0; o >>= 1) contrib += __shfl_xor_sync(0xffffffffu, contrib, o);
            ex += contrib;
            end = pmask ? 0 : start;
        }
        if (tid == 0) {
            if (lb > 0) { __threadfence(); atomicExch(&state[lb], FLAG_P | (ex + total)); }
            s_prefix = ex;
        }
    }
    __syncthreads();
    int p = s_prefix + ex_in;
    int e0 = p, e1 = e0 + v.x, e2 = e1 + v.y, e3 = e2 + v.z;
    if (base + 3 < NNODES) {
        *reinterpret_cast<int4*>(&off[base]) = make_int4(e0, e1, e2, e3);
        *reinterpret_cast<int4*>(&cur[base]) = make_int4(e0, e1, e2, e3);
    } else {
        if (base + 0 < NNODES) { off[base + 0] = e0; cur[base + 0] = e0; }
        if (base + 1 < NNODES) { off[base + 1] = e1; cur[base + 1] = e1; }
        if (base + 2 < NNODES) { off[base + 2] = e2; cur[base + 2] = e2; }
    }
}

// GEMM + attention-dot epilogue. 256 threads. BM = (256/(BN/4))*4 rows/block.
template <int BN, bool TWO>
__device__ void dev_gemm_dots(const float* __restrict__ A1, const float* __restrict__ A2,
                              const float* __restrict__ W,
                              const float* __restrict__ a_src, const float* __restrict__ a_dst,
                              float* __restrict__ C, float* __restrict__ asv,
                              float* __restrict__ adv, int bid) {
    constexpr int K = TWO ? 128 : 64;
    constexpr int NCOLT = BN / 4;
    constexpr int NROWT = 256 / NCOLT;
    constexpr int BM = NROWT * 4;
    __shared__ float Ws[K * BN];

    int tid = threadIdx.x;
    for (int idx = tid; idx < K * BN; idx += 256) Ws[idx] = W[idx];
    __syncthreads();

    int tcol = tid % NCOLT;
    int trow = tid / NCOLT;
    int n0 = tcol * 4;
    int r0 = bid * BM + trow * 4;

    float acc[4][4] = {};
    bool val[4];
    #pragma unroll
    for (int i = 0; i < 4; i++) val[i] = (r0 + i) < NNODES;

    #pragma unroll
    for (int seg = 0; seg < (TWO ? 2 : 1); seg++) {
        const float* A = (seg == 0) ? A1 : A2;
        #pragma unroll 4
        for (int k4 = 0; k4 < 16; k4++) {
            float a[4][4];
            #pragma unroll
            for (int i = 0; i < 4; i++) {
                float4 t = val[i]
                    ? *reinterpret_cast<const float4*>(&A[(size_t)(r0 + i) * 64 + k4 * 4])
                    : make_float4(0.f, 0.f, 0.f, 0.f);
                a[i][0] = t.x; a[i][1] = t.y; a[i][2] = t.z; a[i][3] = t.w;
            }
            #pragma unroll
            for (int s = 0; s < 4; s++) {
                float4 wv = *reinterpret_cast<const float4*>(
                    &Ws[(seg * 64 + k4 * 4 + s) * BN + n0]);
                #pragma unroll
                for (int i = 0; i < 4; i++) {
                    acc[i][0] += a[i][s] * wv.x;
                    acc[i][1] += a[i][s] * wv.y;
                    acc[i][2] += a[i][s] * wv.z;
                    acc[i][3] += a[i][s] * wv.w;
                }
            }
        }
    }
    #pragma unroll
    for (int i = 0; i < 4; i++) {
        if (val[i]) {
            *reinterpret_cast<float4*>(&C[(size_t)(r0 + i) * BN + n0]) =
                make_float4(acc[i][0], acc[i][1], acc[i][2], acc[i][3]);
        }
    }
    // fused attention dots
    float4 as4 = *reinterpret_cast<const float4*>(&a_src[n0]);
    float4 ad4 = *reinterpret_cast<const float4*>(&a_dst[n0]);
    float s_par[4], d_par[4];
    #pragma unroll
    for (int i = 0; i < 4; i++) {
        s_par[i] = acc[i][0] * as4.x + acc[i][1] * as4.y + acc[i][2] * as4.z + acc[i][3] * as4.w;
        d_par[i] = acc[i][0] * ad4.x + acc[i][1] * ad4.y + acc[i][2] * ad4.z + acc[i][3] * ad4.w;
    }
    #pragma unroll
    for (int o = NCOLT / 2; o > 0; o >>= 1) {
        #pragma unroll
        for (int i = 0; i < 4; i++) {
            s_par[i] += __shfl_xor_sync(0xffffffffu, s_par[i], o);
            d_par[i] += __shfl_xor_sync(0xffffffffu, d_par[i], o);
        }
    }
    if (tcol == 0) {
        #pragma unroll
        for (int i = 0; i < 4; i++) {
            if (val[i]) { asv[r0 + i] = s_par[i]; adv[r0 + i] = d_par[i]; }
        }
    }
}

// GAT aggregation F=64, warp per node, unnormalized softmax (e bounded).
template <bool DO_ELU>
__device__ void dev_agg64(const float* __restrict__ h, const float* __restrict__ asv,
                          const float* __restrict__ adv, const int* __restrict__ off,
                          const int* __restrict__ deg, const int* __restrict__ srcs,
                          const float* __restrict__ bias, float* __restrict__ out, int bid) {
    const int i = bid * 8 + (threadIdx.x >> 5);
    const int lane = threadIdx.x & 31;
    const float ad_i = __ldg(&adv[i]);
    const int base = __ldg(&off[i]);
    const int d = __ldg(&deg[i]);

    float wself = __expf(lrelu(__ldg(&asv[i]) + ad_i));
    float denom = wself;
    float acc0 = wself * h[(size_t)i * 64 + lane];
    float acc1 = wself * h[(size_t)i * 64 + 32 + lane];

    for (int k0 = 0; k0 < d; k0 += 32) {
        int kk = k0 + lane;
        int j = 0; float wv = 0.f;
        if (kk < d) {
            j = __ldg(&srcs[base + kk]);
            wv = __expf(lrelu(__ldg(&asv[j]) + ad_i));
        }
        float ws = wv;
        #pragma unroll
        for (int o = 16; o > 0; o >>= 1) ws += __shfl_xor_sync(0xffffffffu, ws, o);
        denom += ws;

        int cnt = min(32, d - k0);
        int k = 0;
        for (; k + 4 <= cnt; k += 4) {
            int j0 = __shfl_sync(0xffffffffu, j, k);
            int j1 = __shfl_sync(0xffffffffu, j, k + 1);
            int j2 = __shfl_sync(0xffffffffu, j, k + 2);
            int j3 = __shfl_sync(0xffffffffu, j, k + 3);
            float w0 = __shfl_sync(0xffffffffu, wv, k);
            float w1 = __shfl_sync(0xffffffffu, wv, k + 1);
            float w2 = __shfl_sync(0xffffffffu, wv, k + 2);
            float w3 = __shfl_sync(0xffffffffu, wv, k + 3);
            float h00 = h[(size_t)j0 * 64 + lane], h01 = h[(size_t)j0 * 64 + 32 + lane];
            float h10 = h[(size_t)j1 * 64 + lane], h11 = h[(size_t)j1 * 64 + 32 + lane];
            float h20 = h[(size_t)j2 * 64 + lane], h21 = h[(size_t)j2 * 64 + 32 + lane];
            float h30 = h[(size_t)j3 * 64 + lane], h31 = h[(size_t)j3 * 64 + 32 + lane];
            acc0 += w0 * h00; acc1 += w0 * h01;
            acc0 += w1 * h10; acc1 += w1 * h11;
            acc0 += w2 * h20; acc1 += w2 * h21;
            acc0 += w3 * h30; acc1 += w3 * h31;
        }
        for (; k < cnt; k++) {
            int jj = __shfl_sync(0xffffffffu, j, k);
            float wk = __shfl_sync(0xffffffffu, wv, k);
            acc0 += wk * h[(size_t)jj * 64 + lane];
            acc1 += wk * h[(size_t)jj * 64 + 32 + lane];
        }
    }
    float inv = 1.0f / (denom + 1e-16f);
    float v0 = acc0 * inv + __ldg(&bias[lane]);
    float v1 = acc1 * inv + __ldg(&bias[32 + lane]);
    out[(size_t)i * 64 + lane]      = DO_ELU ? elu1(v0) : v0;
    out[(size_t)i * 64 + 32 + lane] = DO_ELU ? elu1(v1) : v1;
}

// ============================ fused kernels =================================

__global__ void k_zero() {
    int i = blockIdx.x * blockDim.x + threadIdx.x;
    if (i < NNODES) { g_deg1[i] = 0; g_deg2[i] = 0; }
    if (i < NB98) { g_state1[i] = 0; g_state2[i] = 0; }
    if (i < 16) { g_bnsum[i] = 0.f; g_bnsumsq[i] = 0.f; }
}

// L2: count1 || gemm0(+dots)
__global__ void __launch_bounds__(256) k_count1_gemm0(
    const int* __restrict__ ei1, const float* __restrict__ x1,
    const float* __restrict__ W0, const float* __restrict__ as0,
    const float* __restrict__ ad0) {
    if (blockIdx.x < EB) dev_count(ei1, g_deg1, blockIdx.x);
    else dev_gemm_dots<64, false>(x1, nullptr, W0, as0, ad0,
                                  g_tmpH, g_as, g_ad, blockIdx.x - EB);
}

// L3: scan1(lookback) || count2
__global__ void __launch_bounds__(256) k_scan1_count2(const int* __restrict__ ei2) {
    if (blockIdx.x < NB98)
        dev_scan_lookback(g_deg1, g_off1, g_cursor1, g_state1, blockIdx.x);
    else
        dev_count(ei2, g_deg2, blockIdx.x - NB98);
}

// L4: scan2(lookback) || scatter1
__global__ void __launch_bounds__(256) k_scan2_scatter1(const int* __restrict__ ei1) {
    if (blockIdx.x < NB98)
        dev_scan_lookback(g_deg2, g_off2, g_cursor2, g_state2, blockIdx.x);
    else
        dev_scatter(ei1, g_cursor1, g_srcs1, blockIdx.x - NB98);
}

// L5: agg0 || scatter2
__global__ void __launch_bounds__(256) k_agg0_scatter2(
    const int* __restrict__ ei2, const float* __restrict__ b0) {
    if (blockIdx.x < WARPB)
        dev_agg64<true>(g_tmpH, g_as, g_ad, g_off1, g_deg1, g_srcs1, b0, g_h0, blockIdx.x);
    else
        dev_scatter(ei2, g_cursor2, g_srcs2, blockIdx.x - WARPB);
}

// L6: gemm_dots layer1 (K=128: h0 | x2)
__global__ void __launch_bounds__(256) k_gemm1(
    const float* __restrict__ x2, const float* __restrict__ W1,
    const float* __restrict__ as1, const float* __restrict__ ad1) {
    dev_gemm_dots<64, true>(g_h0, x2, W1, as1, ad1, g_tmpH, g_as, g_ad, blockIdx.x);
}

// L7: agg1
__global__ void __launch_bounds__(256) k_agg1(const float* __restrict__ b1) {
    dev_agg64<true>(g_tmpH, g_as, g_ad, g_off2, g_deg2, g_srcs2, b1, g_h1, blockIdx.x);
}

// L8: gemm_dots layer2 (BN=16, BM=256; K=128: h0 | h1)
__global__ void __launch_bounds__(256) k_gemm2(
    const float* __restrict__ W2, const float* __restrict__ as2,
    const float* __restrict__ ad2) {
    dev_gemm_dots<16, true>(g_h0, g_h1, W2, as2, ad2, g_tmpS, g_as, g_ad, blockIdx.x);
}

// L9: agg layer2 (F=16) with fused BN statistics
__global__ void __launch_bounds__(256) k_agg2_bn(
    const float* __restrict__ b2, float* __restrict__ out) {
    __shared__ float shs[16], shs2[16];
    if (threadIdx.x < 16) { shs[threadIdx.x] = 0.f; shs2[threadIdx.x] = 0.f; }
    __syncthreads();

    const float* __restrict__ h = g_tmpS;
    const int i = blockIdx.x * 8 + (threadIdx.x >> 5);
    const int lane = threadIdx.x & 31;
    const int e = lane >> 4;
    const int f = lane & 15;
    const float ad_i = __ldg(&g_ad[i]);
    const int base = __ldg(&g_off2[i]);
    const int d = __ldg(&g_deg2[i]);

    float wself = __expf(lrelu(__ldg(&g_as[i]) + ad_i));
    float denom = wself;
    float acc = (e == 0) ? wself * h[(size_t)i * 16 + f] : 0.f;

    for (int k0 = 0; k0 < d; k0 += 32) {
        int kk = k0 + lane;
        int j = 0; float wv = 0.f;
        if (kk < d) {
            j = __ldg(&g_srcs2[base + kk]);
            wv = __expf(lrelu(__ldg(&g_as[j]) + ad_i));
        }
        float ws = wv;
        #pragma unroll
        for (int o = 16; o > 0; o >>= 1) ws += __shfl_xor_sync(0xffffffffu, ws, o);
        denom += ws;

        int cnt = min(32, d - k0);
        int k = 0;
        for (; k + 4 <= cnt; k += 4) {
            int ja = __shfl_sync(0xffffffffu, j, k + e);
            int jb = __shfl_sync(0xffffffffu, j, k + 2 + e);
            float wa = __shfl_sync(0xffffffffu, wv, k + e);
            float wb = __shfl_sync(0xffffffffu, wv, k + 2 + e);
            acc += wa * h[(size_t)ja * 16 + f] + wb * h[(size_t)jb * 16 + f];
        }
        for (; k < cnt; k += 2) {
            int km = min(k + e, 31);
            int ja = __shfl_sync(0xffffffffu, j, km);
            float wa = __shfl_sync(0xffffffffu, wv, km);
            if (k + e < cnt) acc += wa * h[(size_t)ja * 16 + f];
        }
    }
    acc += __shfl_xor_sync(0xffffffffu, acc, 16);
    float inv = 1.0f / (denom + 1e-16f);
    if (e == 0) {
        float v = acc * inv + __ldg(&b2[f]);
        out[(size_t)i * 16 + f] = v;
        atomicAdd(&shs[f], v);
        atomicAdd(&shs2[f], v * v);
    }
    __syncthreads();
    if (threadIdx.x < 16) {
        atomicAdd(&g_bnsum[threadIdx.x], shs[threadIdx.x]);
        atomicAdd(&g_bnsumsq[threadIdx.x], shs2[threadIdx.x]);
    }
}

// L10: BN + log_softmax in place
__global__ void __launch_bounds__(256) k_bn_lsm(
    float* __restrict__ out, const float* __restrict__ gamma,
    const float* __restrict__ beta) {
    int i = blockIdx.x * blockDim.x + threadIdx.x;
    if (i >= NNODES) return;
    float y[16];
    float maxv = -1e30f;
    const float invN = 1.0f / (float)NNODES;
    #pragma unroll
    for (int c = 0; c < 16; c++) {
        float mu = g_bnsum[c] * invN;
        float var = g_bnsumsq[c] * invN - mu * mu;
        float v = out[(size_t)i * 16 + c];
        float yy = (v - mu) * rsqrtf(var + BN_EPS_C) * gamma[c] + beta[c];
        y[c] = yy;
        maxv = fmaxf(maxv, yy);
    }
    float s = 0.f;
    #pragma unroll
    for (int c = 0; c < 16; c++) s += expf(y[c] - maxv);
    float lse = maxv + logf(s);
    #pragma unroll
    for (int c = 0; c < 16; c++) out[(size_t)i * 16 + c] = y[c] - lse;
}

// ----------------------------- driver ---------------------------------------
extern "C" void kernel_launch(void* const* d_in, const int* in_sizes, int n_in,
                              void* d_out, int out_size) {
    const float* x1    = (const float*)d_in[0];
    const float* x2    = (const float*)d_in[1];
    const int*   ei1   = (const int*)d_in[2];
    const int*   ei2   = (const int*)d_in[3];
    const float* W0    = (const float*)d_in[4];
    const float* asrc0 = (const float*)d_in[5];
    const float* adst0 = (const float*)d_in[6];
    const float* b0    = (const float*)d_in[7];
    const float* W1    = (const float*)d_in[8];
    const float* asrc1 = (const float*)d_in[9];
    const float* adst1 = (const float*)d_in[10];
    const float* b1    = (const float*)d_in[11];
    const float* W2    = (const float*)d_in[12];
    const float* asrc2 = (const float*)d_in[13];
    const float* adst2 = (const float*)d_in[14];
    const float* b2    = (const float*)d_in[15];
    const float* gamma = (const float*)d_in[16];
    const float* beta  = (const float*)d_in[17];
    float* out = (float*)d_out;

    k_zero<<<GB256, 256>>>();                                            // L1
    k_count1_gemm0<<<EB + GB64, 256>>>(ei1, x1, W0, asrc0, adst0);       // L2
    k_scan1_count2<<<NB98 + EB, 256>>>(ei2);                             // L3
    k_scan2_scatter1<<<NB98 + EB, 256>>>(ei1);                           // L4
    k_agg0_scatter2<<<WARPB + EB, 256>>>(ei2, b0);                       // L5
    k_gemm1<<<GB64, 256>>>(x2, W1, asrc1, adst1);                        // L6
    k_agg1<<<WARPB, 256>>>(b1);                                          // L7
    k_gemm2<<<GB256, 256>>>(W2, asrc2, adst2);                           // L8
    k_agg2_bn<<<WARPB, 256>>>(b2, out);                                  // L9
    k_bn_lsm<<<GB256, 256>>>(out, gamma, beta);                          // L10
}